// round 3
// baseline (speedup 1.0000x reference)
#include <cuda_runtime.h>
#include <cuda_bf16.h>
#include <cstdint>

// ===================== problem constants =====================
#define N_ROWS 16384
#define DIMK   256
#define TILE   128
#define NTILES (N_ROWS / TILE)   // 128

// exp((s-1)/T) = 2^(s*C1 - C1),  C1 = log2(e)/T,  T = 0.07
#define C1F   20.60992915555662f
#define INV_T 14.285714285714286f

// ===================== device globals (no allocs allowed) =====================
__device__ uint4 g_emb4[N_ROWS * DIMK / 8];   // normalized bf16 rows, 8 bf16 per uint4
__device__ float g_partial[NTILES];

// ===================== helpers =====================
__device__ __forceinline__ uint32_t smem_to_u32(const void* smem_ptr) {
    uint32_t addr;
    asm("{ .reg .u64 tmp; cvta.to.shared.u64 tmp, %1; cvt.u32.u64 %0, tmp; }"
        : "=r"(addr) : "l"(smem_ptr));
    return addr;
}

__device__ __forceinline__ void ldsm4(uint32_t* r, uint32_t addr) {
    asm volatile("ldmatrix.sync.aligned.m8n8.x4.shared.b16 {%0,%1,%2,%3}, [%4];"
        : "=r"(r[0]), "=r"(r[1]), "=r"(r[2]), "=r"(r[3]) : "r"(addr));
}

__device__ __forceinline__ void mma16816(float* c, const uint32_t* a, uint32_t b0, uint32_t b1) {
    asm volatile(
        "mma.sync.aligned.m16n8k16.row.col.f32.bf16.bf16.f32 "
        "{%0,%1,%2,%3}, {%4,%5,%6,%7}, {%8,%9}, {%0,%1,%2,%3};"
        : "+f"(c[0]), "+f"(c[1]), "+f"(c[2]), "+f"(c[3])
        : "r"(a[0]), "r"(a[1]), "r"(a[2]), "r"(a[3]), "r"(b0), "r"(b1));
}

#define CP_ASYNC16(dst_u32, src_ptr) \
    asm volatile("cp.async.cg.shared.global [%0], [%1], 16;" \
        :: "r"(dst_u32), "l"(src_ptr) : "memory")
#define CP_COMMIT() asm volatile("cp.async.commit_group;" ::: "memory")
#define CP_WAIT0()  asm volatile("cp.async.wait_group 0;" ::: "memory")
#define CP_WAIT1()  asm volatile("cp.async.wait_group 1;" ::: "memory")

// ===================== kernel 1: row L2-normalize -> bf16 =====================
__global__ __launch_bounds__(256) void norm_kernel(const float* __restrict__ in) {
    int wid = threadIdx.x >> 5;
    int lane = threadIdx.x & 31;
    int row = blockIdx.x * 8 + wid;

    const float4* p = reinterpret_cast<const float4*>(in + (size_t)row * DIMK) + lane * 2;
    float4 a = p[0];
    float4 b = p[1];
    float ss = a.x * a.x + a.y * a.y + a.z * a.z + a.w * a.w
             + b.x * b.x + b.y * b.y + b.z * b.z + b.w * b.w;
#pragma unroll
    for (int o = 16; o > 0; o >>= 1) ss += __shfl_xor_sync(0xffffffffu, ss, o);

    float nrm = fmaxf(sqrtf(ss), 1e-12f);
    float sc = 1.0f / nrm;

    __nv_bfloat162 h0 = __floats2bfloat162_rn(a.x * sc, a.y * sc);
    __nv_bfloat162 h1 = __floats2bfloat162_rn(a.z * sc, a.w * sc);
    __nv_bfloat162 h2 = __floats2bfloat162_rn(b.x * sc, b.y * sc);
    __nv_bfloat162 h3 = __floats2bfloat162_rn(b.z * sc, b.w * sc);
    uint4 u;
    u.x = *reinterpret_cast<uint32_t*>(&h0);
    u.y = *reinterpret_cast<uint32_t*>(&h1);
    u.z = *reinterpret_cast<uint32_t*>(&h2);
    u.w = *reinterpret_cast<uint32_t*>(&h3);
    g_emb4[(size_t)row * 32 + lane] = u;
}

// ===================== kernel 2: mma.sync GEMM + fused shifted-exp LSE =====================
// Dynamic SMEM layout:
//   A tile @ 0      : 64KB (128 rows x 512B, 16B-chunk XOR swizzle)
//   B buf0 @ 65536  : 64KB
//   B buf1 @ 131072 : 64KB
//   tail   @ 196608 : s_rowp[128*4] (2KB), s_diag[128] (512B), s_red[8] (32B)
#define SM_A     0
#define SM_B     65536
#define SM_TAIL  196608
#define OFF_ROWP 0
#define OFF_DIAG 2048
#define OFF_RED  2560
#define DYN_SMEM (196608 + 2048 + 512 + 64)

// Load a 128-row tile of g_emb4 into smem with per-row 16B-chunk XOR swizzle:
// chunk j of row i lands at (j ^ (i&7)). 256 threads, 16B each, 16 iters.
__device__ __forceinline__ void load_tile_async(uint32_t dst_u, int row0, int tid) {
#pragma unroll
    for (int it = 0; it < 16; ++it) {
        int c = tid + it * 256;          // 0..4095
        int i = c >> 5;                  // row 0..127
        int j = c & 31;                  // 16B chunk 0..31
        uint32_t off = ((uint32_t)i << 9) + ((uint32_t)(j ^ (i & 7)) << 4);
        CP_ASYNC16(dst_u + off, &g_emb4[(size_t)(row0 + i) * 32 + j]);
    }
}

__global__ __launch_bounds__(256, 1) void gemm_lse_kernel() {
    extern __shared__ char smem[];
    uint32_t su = smem_to_u32(smem);

    int tid = threadIdx.x;
    int lane = tid & 31;
    int wid = tid >> 5;
    int warp_m = wid >> 2;   // 0..1  (64 rows each)
    int warp_n = wid & 3;    // 0..3  (32 cols each)

    float* s_rowp = reinterpret_cast<float*>(smem + SM_TAIL + OFF_ROWP);
    float* s_diag = reinterpret_cast<float*>(smem + SM_TAIL + OFF_DIAG);
    float* s_red  = reinterpret_cast<float*>(smem + SM_TAIL + OFF_RED);

    // Prologue: A tile (this CTA's rows) + first B tile
    load_tile_async(su + SM_A, (int)blockIdx.x * TILE, tid);
    load_tile_async(su + SM_B, 0, tid);
    CP_COMMIT();
    CP_WAIT0();
    __syncthreads();

    // Precompute ldmatrix addressing
    // A: lane i supplies row (lane&15), col-half (lane>>4)
    uint32_t a_base[4];
    uint32_t a_rx[4];
#pragma unroll
    for (int mf = 0; mf < 4; mf++) {
        int r = warp_m * 64 + mf * 16 + (lane & 15);
        a_base[mf] = su + SM_A + ((uint32_t)r << 9);
        a_rx[mf] = (uint32_t)(r & 7);
    }
    uint32_t a_hi = (uint32_t)(lane >> 4);          // +8 cols -> +1 chunk

    // B: lane i supplies n-row (lane&7) + 8*(lane>=16), k-half ((lane>>3)&1)
    int nB = (lane & 7) + ((lane >> 4) << 3);
    uint32_t b_roff[2];
#pragma unroll
    for (int np = 0; np < 2; np++)
        b_roff[np] = (uint32_t)((warp_n * 32 + np * 16 + nB) << 9);
    uint32_t b_rx = (uint32_t)(lane & 7);           // (row_B & 7)
    uint32_t b_kb = (uint32_t)((lane >> 3) & 1);

    float rowacc[8];
#pragma unroll
    for (int i = 0; i < 8; i++) rowacc[i] = 0.0f;

    const int mytile = (int)blockIdx.x;
    const int g = lane >> 2;        // accumulator row-in-frag
    const int tg = lane & 3;        // accumulator col pair

    for (int t = 0; t < NTILES; t++) {
        // Prefetch next B tile (overlaps with this tile's MMA)
        if (t + 1 < NTILES) {
            load_tile_async(su + SM_B + ((t + 1) & 1) * 65536, (t + 1) * TILE, tid);
            CP_COMMIT();
            CP_WAIT1();
        } else {
            CP_WAIT0();
        }
        __syncthreads();   // B(t) visible to all warps

        uint32_t b_u = su + SM_B + (t & 1) * 65536;

        float acc[4][4][4];
#pragma unroll
        for (int mf = 0; mf < 4; mf++)
#pragma unroll
            for (int nf = 0; nf < 4; nf++)
#pragma unroll
                for (int e = 0; e < 4; e++) acc[mf][nf][e] = 0.0f;

#pragma unroll
        for (int ks = 0; ks < 16; ks++) {
            uint32_t a[4][4];
#pragma unroll
            for (int mf = 0; mf < 4; mf++) {
                uint32_t ch = ((uint32_t)(ks * 2) + a_hi) ^ a_rx[mf];
                ldsm4(a[mf], a_base[mf] + (ch << 4));
            }
            uint32_t b[2][4];
#pragma unroll
            for (int np = 0; np < 2; np++) {
                uint32_t ch = ((uint32_t)(ks * 2) + b_kb) ^ b_rx;
                ldsm4(b[np], b_u + b_roff[np] + (ch << 4));
            }
#pragma unroll
            for (int mf = 0; mf < 4; mf++)
#pragma unroll
                for (int np = 0; np < 2; np++) {
                    mma16816(acc[mf][np * 2 + 0], a[mf], b[np][0], b[np][1]);
                    mma16816(acc[mf][np * 2 + 1], a[mf], b[np][2], b[np][3]);
                }
        }

        // Fused epilogue: term = exp((s-1)/T) = 2^(s*C1 - C1); accumulate per row.
        bool diag_tile = (t == mytile);
#pragma unroll
        for (int mf = 0; mf < 4; mf++) {
#pragma unroll
            for (int nf = 0; nf < 4; nf++) {
#pragma unroll
                for (int e = 0; e < 4; e++) {
                    float s = acc[mf][nf][e];
                    float tv = fmaf(s, C1F, -C1F);
                    float mk = tv + 12582912.0f;           // rint via magic number
                    float kf = mk - 12582912.0f;
                    float f = tv - kf;                      // in [-0.5, 0.5]
                    float p = fmaf(f, 0.0013333558f, 0.0096181291f);
                    p = fmaf(f, p, 0.055504109f);
                    p = fmaf(f, p, 0.24022651f);
                    p = fmaf(f, p, 0.69314718f);
                    p = fmaf(f, p, 1.0f);
                    int eb = (__float_as_int(mk) << 23) + 0x3F800000;   // 2^kf
                    float v = p * __int_as_float(eb);
                    rowacc[mf * 2 + (e >> 1)] += v;

                    if (diag_tile) {
                        int r = warp_m * 64 + mf * 16 + g + ((e >> 1) << 3);
                        int c = warp_n * 32 + nf * 8 + (tg << 1) + (e & 1);
                        if (r == c) s_diag[r] = s;
                    }
                }
            }
        }
        __syncthreads();   // epilogue done before buf[t&1] is overwritten at iter t+1's prefetch of t+2
    }

    // Per-row partial sums: lanes tg=0..3 share the same rows -> shfl reduce.
#pragma unroll
    for (int i = 0; i < 8; i++) {
        float v = rowacc[i];
        v += __shfl_xor_sync(0xffffffffu, v, 1);
        v += __shfl_xor_sync(0xffffffffu, v, 2);
        if (tg == 0) {
            int r = warp_m * 64 + (i >> 1) * 16 + g + ((i & 1) << 3);
            s_rowp[r * 4 + warp_n] = v;
        }
    }
    __syncthreads();

    float li = 0.0f;
    if (tid < 128) {
        float S = s_rowp[tid * 4 + 0] + s_rowp[tid * 4 + 1]
                + s_rowp[tid * 4 + 2] + s_rowp[tid * 4 + 3];
        li = (1.0f - s_diag[tid]) * INV_T + logf(S);
#pragma unroll
        for (int o = 16; o > 0; o >>= 1) li += __shfl_xor_sync(0xffffffffu, li, o);
        if (lane == 0) s_red[wid] = li;
    }
    __syncthreads();
    if (tid == 0)
        g_partial[blockIdx.x] = s_red[0] + s_red[1] + s_red[2] + s_red[3];
}

// ===================== kernel 3: final reduction =====================
__global__ __launch_bounds__(128) void reduce_kernel(float* __restrict__ out) {
    __shared__ float r[4];
    int tid = threadIdx.x;
    int wid = tid >> 5;
    int lane = tid & 31;
    float v = g_partial[tid];
#pragma unroll
    for (int o = 16; o > 0; o >>= 1) v += __shfl_xor_sync(0xffffffffu, v, o);
    if (lane == 0) r[wid] = v;
    __syncthreads();
    if (tid == 0)
        out[0] = (r[0] + r[1] + r[2] + r[3]) * (1.0f / (float)N_ROWS);
}

// ===================== launch =====================
extern "C" void kernel_launch(void* const* d_in, const int* in_sizes, int n_in,
                              void* d_out, int out_size) {
    (void)in_sizes; (void)n_in; (void)out_size;
    const float* emb = (const float*)d_in[0];

    cudaFuncSetAttribute(gemm_lse_kernel,
                         cudaFuncAttributeMaxDynamicSharedMemorySize, DYN_SMEM);

    norm_kernel<<<N_ROWS / 8, 256>>>(emb);
    gemm_lse_kernel<<<NTILES, 256, DYN_SMEM>>>();
    reduce_kernel<<<1, 128>>>((float*)d_out);
}

// round 4
// speedup vs baseline: 1.1895x; 1.1895x over previous
#include <cuda_runtime.h>
#include <cuda_bf16.h>
#include <cstdint>

// ===================== problem constants =====================
#define N_ROWS 16384
#define DIMK   256
#define TILE   128
#define NTILES (N_ROWS / TILE)   // 128

// exp((s-1)/T) = 2^(s*C1 - C1),  C1 = log2(e)/T,  T = 0.07
#define C1F   20.60992915555662f
#define INV_T 14.285714285714286f

// ===================== device globals (no allocs allowed) =====================
__device__ uint4 g_emb4[N_ROWS * DIMK / 8];   // normalized bf16 rows, 8 bf16 per uint4
__device__ float g_partial[NTILES];

// ===================== helpers =====================
__device__ __forceinline__ uint32_t smem_to_u32(const void* smem_ptr) {
    uint32_t addr;
    asm("{ .reg .u64 tmp; cvta.to.shared.u64 tmp, %1; cvt.u32.u64 %0, tmp; }"
        : "=r"(addr) : "l"(smem_ptr));
    return addr;
}

__device__ __forceinline__ void ldsm4(uint32_t* r, uint32_t addr) {
    asm volatile("ldmatrix.sync.aligned.m8n8.x4.shared.b16 {%0,%1,%2,%3}, [%4];"
        : "=r"(r[0]), "=r"(r[1]), "=r"(r[2]), "=r"(r[3]) : "r"(addr));
}

__device__ __forceinline__ void mma16816(float* c, const uint32_t* a, uint32_t b0, uint32_t b1) {
    asm volatile(
        "mma.sync.aligned.m16n8k16.row.col.f32.bf16.bf16.f32 "
        "{%0,%1,%2,%3}, {%4,%5,%6,%7}, {%8,%9}, {%0,%1,%2,%3};"
        : "+f"(c[0]), "+f"(c[1]), "+f"(c[2]), "+f"(c[3])
        : "r"(a[0]), "r"(a[1]), "r"(a[2]), "r"(a[3]), "r"(b0), "r"(b1));
}

// First K-step: D = A*B + 0  (avoids separate accumulator zeroing)
__device__ __forceinline__ void mma16816_z(float* c, const uint32_t* a, uint32_t b0, uint32_t b1) {
    asm volatile(
        "mma.sync.aligned.m16n8k16.row.col.f32.bf16.bf16.f32 "
        "{%0,%1,%2,%3}, {%4,%5,%6,%7}, {%8,%9}, {%10,%10,%10,%10};"
        : "=f"(c[0]), "=f"(c[1]), "=f"(c[2]), "=f"(c[3])
        : "r"(a[0]), "r"(a[1]), "r"(a[2]), "r"(a[3]), "r"(b0), "r"(b1), "f"(0.0f));
}

__device__ __forceinline__ float ex2f(float x) {
    float r;
    asm("ex2.approx.f32 %0, %1;" : "=f"(r) : "f"(x));
    return r;
}

#define CP_ASYNC16(dst_u32, src_ptr) \
    asm volatile("cp.async.cg.shared.global [%0], [%1], 16;" \
        :: "r"(dst_u32), "l"(src_ptr) : "memory")
#define CP_COMMIT() asm volatile("cp.async.commit_group;" ::: "memory")
#define CP_WAIT0()  asm volatile("cp.async.wait_group 0;" ::: "memory")
#define CP_WAIT1()  asm volatile("cp.async.wait_group 1;" ::: "memory")

// ===================== kernel 1: row L2-normalize -> bf16 =====================
__global__ __launch_bounds__(256) void norm_kernel(const float* __restrict__ in) {
    int wid = threadIdx.x >> 5;
    int lane = threadIdx.x & 31;
    int row = blockIdx.x * 8 + wid;

    const float4* p = reinterpret_cast<const float4*>(in + (size_t)row * DIMK) + lane * 2;
    float4 a = p[0];
    float4 b = p[1];
    float ss = a.x * a.x + a.y * a.y + a.z * a.z + a.w * a.w
             + b.x * b.x + b.y * b.y + b.z * b.z + b.w * b.w;
#pragma unroll
    for (int o = 16; o > 0; o >>= 1) ss += __shfl_xor_sync(0xffffffffu, ss, o);

    float nrm = fmaxf(sqrtf(ss), 1e-12f);
    float sc = 1.0f / nrm;

    __nv_bfloat162 h0 = __floats2bfloat162_rn(a.x * sc, a.y * sc);
    __nv_bfloat162 h1 = __floats2bfloat162_rn(a.z * sc, a.w * sc);
    __nv_bfloat162 h2 = __floats2bfloat162_rn(b.x * sc, b.y * sc);
    __nv_bfloat162 h3 = __floats2bfloat162_rn(b.z * sc, b.w * sc);
    uint4 u;
    u.x = *reinterpret_cast<uint32_t*>(&h0);
    u.y = *reinterpret_cast<uint32_t*>(&h1);
    u.z = *reinterpret_cast<uint32_t*>(&h2);
    u.w = *reinterpret_cast<uint32_t*>(&h3);
    g_emb4[(size_t)row * 32 + lane] = u;
}

// ===================== kernel 2: mma.sync GEMM + pipelined shifted-exp LSE =====================
// Dynamic SMEM layout:
//   A tile @ 0      : 64KB (128 rows x 512B, 16B-chunk XOR swizzle)
//   B buf0 @ 65536  : 64KB
//   B buf1 @ 131072 : 64KB
//   tail   @ 196608 : s_rowp[128*4] (2KB), s_diag[128] (512B), s_red[8] (32B)
#define SM_A     0
#define SM_B     65536
#define SM_TAIL  196608
#define OFF_ROWP 0
#define OFF_DIAG 2048
#define OFF_RED  2560
#define DYN_SMEM (196608 + 2048 + 512 + 64)

__device__ __forceinline__ void load_tile_async(uint32_t dst_u, int row0, int tid) {
#pragma unroll
    for (int it = 0; it < 16; ++it) {
        int c = tid + it * 256;          // 0..4095
        int i = c >> 5;                  // row 0..127
        int j = c & 31;                  // 16B chunk 0..31
        uint32_t off = ((uint32_t)i << 9) + ((uint32_t)(j ^ (i & 7)) << 4);
        CP_ASYNC16(dst_u + off, &g_emb4[(size_t)(row0 + i) * 32 + j]);
    }
}

// One epilogue step: value v (0..63) of the previous tile's accumulators.
__device__ __forceinline__ void epi_step(
    const float (&accP)[4][4][4], int v, float (&rowacc)[8],
    float* s_diag, bool diag_tile,
    int warp_m, int warp_n, int g, int tg)
{
    int mf = v >> 4, nf = (v >> 2) & 3, e = v & 3;
    float s = accP[mf][nf][e];
    float ex = ex2f(fmaf(s, C1F, -C1F));    // exp((s-1)/T)
    rowacc[mf * 2 + (e >> 1)] += ex;
    if (diag_tile) {
        int r = warp_m * 64 + mf * 16 + g + ((e >> 1) << 3);
        int c = warp_n * 32 + nf * 8 + (tg << 1) + (e & 1);
        if (r == c) s_diag[r] = s;
    }
}

// One tile iteration: MMA(tile t) into accC, epilogue(tile t-1) from accP interleaved.
template <bool DO_EPI>
__device__ __forceinline__ void tile_iter(
    int t, float (&accC)[4][4][4], float (&accP)[4][4][4],
    uint32_t su, int tid,
    const uint32_t (&a_base)[4], const uint32_t (&a_rx)[4], uint32_t a_hi,
    const uint32_t (&b_roff)[2], uint32_t b_rx, uint32_t b_kb,
    float (&rowacc)[8], float* s_diag, int mytile,
    int warp_m, int warp_n, int g, int tg)
{
    if (t + 1 < NTILES) {
        load_tile_async(su + SM_B + ((t + 1) & 1) * 65536, (t + 1) * TILE, tid);
        CP_COMMIT();
        CP_WAIT1();
    } else {
        CP_WAIT0();
    }
    __syncthreads();   // B(t) visible; all warps past reads of the buffer being refilled

    uint32_t b_u = su + SM_B + (t & 1) * 65536;
    bool diag_tile = DO_EPI && ((t - 1) == mytile);

#pragma unroll
    for (int ks = 0; ks < 16; ks++) {
        uint32_t a[4][4];
#pragma unroll
        for (int mf = 0; mf < 4; mf++) {
            uint32_t ch = ((uint32_t)(ks * 2) + a_hi) ^ a_rx[mf];
            ldsm4(a[mf], a_base[mf] + (ch << 4));
        }
        uint32_t b[2][4];
#pragma unroll
        for (int np = 0; np < 2; np++) {
            uint32_t ch = ((uint32_t)(ks * 2) + b_kb) ^ b_rx;
            ldsm4(b[np], b_u + b_roff[np] + (ch << 4));
        }
#pragma unroll
        for (int mf = 0; mf < 4; mf++)
#pragma unroll
            for (int np = 0; np < 2; np++) {
                if (ks == 0) {
                    mma16816_z(accC[mf][np * 2 + 0], a[mf], b[np][0], b[np][1]);
                    mma16816_z(accC[mf][np * 2 + 1], a[mf], b[np][2], b[np][3]);
                } else {
                    mma16816(accC[mf][np * 2 + 0], a[mf], b[np][0], b[np][1]);
                    mma16816(accC[mf][np * 2 + 1], a[mf], b[np][2], b[np][3]);
                }
            }
        // Interleave 4 epilogue values of the previous tile per K-step (64 total).
        if (DO_EPI) {
#pragma unroll
            for (int u = 0; u < 4; u++)
                epi_step(accP, ks * 4 + u, rowacc, s_diag, diag_tile,
                         warp_m, warp_n, g, tg);
        }
    }
    __syncthreads();   // all warps done reading buf[t&1] before iter t+1 refills it at t+2's prefetch
}

__global__ __launch_bounds__(256, 1) void gemm_lse_kernel() {
    extern __shared__ char smem[];
    uint32_t su = smem_to_u32(smem);

    int tid = threadIdx.x;
    int lane = tid & 31;
    int wid = tid >> 5;
    int warp_m = wid >> 2;   // 0..1  (64 rows each)
    int warp_n = wid & 3;    // 0..3  (32 cols each)

    float* s_rowp = reinterpret_cast<float*>(smem + SM_TAIL + OFF_ROWP);
    float* s_diag = reinterpret_cast<float*>(smem + SM_TAIL + OFF_DIAG);
    float* s_red  = reinterpret_cast<float*>(smem + SM_TAIL + OFF_RED);

    // Prologue: A tile (this CTA's rows) + first B tile
    load_tile_async(su + SM_A, (int)blockIdx.x * TILE, tid);
    load_tile_async(su + SM_B, 0, tid);
    CP_COMMIT();

    // ldmatrix addressing
    uint32_t a_base[4];
    uint32_t a_rx[4];
#pragma unroll
    for (int mf = 0; mf < 4; mf++) {
        int r = warp_m * 64 + mf * 16 + (lane & 15);
        a_base[mf] = su + SM_A + ((uint32_t)r << 9);
        a_rx[mf] = (uint32_t)(r & 7);
    }
    uint32_t a_hi = (uint32_t)(lane >> 4);

    int nB = (lane & 7) + ((lane >> 4) << 3);
    uint32_t b_roff[2];
#pragma unroll
    for (int np = 0; np < 2; np++)
        b_roff[np] = (uint32_t)((warp_n * 32 + np * 16 + nB) << 9);
    uint32_t b_rx = (uint32_t)(lane & 7);
    uint32_t b_kb = (uint32_t)((lane >> 3) & 1);

    float rowacc[8];
#pragma unroll
    for (int i = 0; i < 8; i++) rowacc[i] = 0.0f;

    const int mytile = (int)blockIdx.x;
    const int g = lane >> 2;
    const int tg = lane & 3;

    float accA[4][4][4], accB[4][4][4];

    // t=0: MMA only; t=1: MMA + epi(0); then steady ping-pong.
    tile_iter<false>(0, accA, accB, su, tid, a_base, a_rx, a_hi, b_roff, b_rx, b_kb,
                     rowacc, s_diag, mytile, warp_m, warp_n, g, tg);
    tile_iter<true>(1, accB, accA, su, tid, a_base, a_rx, a_hi, b_roff, b_rx, b_kb,
                    rowacc, s_diag, mytile, warp_m, warp_n, g, tg);
    for (int t = 2; t < NTILES; t += 2) {
        tile_iter<true>(t, accA, accB, su, tid, a_base, a_rx, a_hi, b_roff, b_rx, b_kb,
                        rowacc, s_diag, mytile, warp_m, warp_n, g, tg);
        tile_iter<true>(t + 1, accB, accA, su, tid, a_base, a_rx, a_hi, b_roff, b_rx, b_kb,
                        rowacc, s_diag, mytile, warp_m, warp_n, g, tg);
    }
    // Final epilogue: tile NTILES-1 lives in accB.
    {
        bool diag_tile = ((NTILES - 1) == mytile);
#pragma unroll
        for (int v = 0; v < 64; v++)
            epi_step(accB, v, rowacc, s_diag, diag_tile, warp_m, warp_n, g, tg);
    }

    // Per-row partial sums: lanes tg=0..3 share rows -> shfl reduce.
#pragma unroll
    for (int i = 0; i < 8; i++) {
        float v = rowacc[i];
        v += __shfl_xor_sync(0xffffffffu, v, 1);
        v += __shfl_xor_sync(0xffffffffu, v, 2);
        if (tg == 0) {
            int r = warp_m * 64 + (i >> 1) * 16 + g + ((i & 1) << 3);
            s_rowp[r * 4 + warp_n] = v;
        }
    }
    __syncthreads();

    float li = 0.0f;
    if (tid < 128) {
        float S = s_rowp[tid * 4 + 0] + s_rowp[tid * 4 + 1]
                + s_rowp[tid * 4 + 2] + s_rowp[tid * 4 + 3];
        li = (1.0f - s_diag[tid]) * INV_T + logf(S);
#pragma unroll
        for (int o = 16; o > 0; o >>= 1) li += __shfl_xor_sync(0xffffffffu, li, o);
        if (lane == 0) s_red[wid] = li;
    }
    __syncthreads();
    if (tid == 0)
        g_partial[blockIdx.x] = s_red[0] + s_red[1] + s_red[2] + s_red[3];
}

// ===================== kernel 3: final reduction =====================
__global__ __launch_bounds__(128) void reduce_kernel(float* __restrict__ out) {
    __shared__ float r[4];
    int tid = threadIdx.x;
    int wid = tid >> 5;
    int lane = tid & 31;
    float v = g_partial[tid];
#pragma unroll
    for (int o = 16; o > 0; o >>= 1) v += __shfl_xor_sync(0xffffffffu, v, o);
    if (lane == 0) r[wid] = v;
    __syncthreads();
    if (tid == 0)
        out[0] = (r[0] + r[1] + r[2] + r[3]) * (1.0f / (float)N_ROWS);
}

// ===================== launch =====================
extern "C" void kernel_launch(void* const* d_in, const int* in_sizes, int n_in,
                              void* d_out, int out_size) {
    (void)in_sizes; (void)n_in; (void)out_size;
    const float* emb = (const float*)d_in[0];

    cudaFuncSetAttribute(gemm_lse_kernel,
                         cudaFuncAttributeMaxDynamicSharedMemorySize, DYN_SMEM);

    norm_kernel<<<N_ROWS / 8, 256>>>(emb);
    gemm_lse_kernel<<<NTILES, 256, DYN_SMEM>>>();
    reduce_kernel<<<1, 128>>>((float*)d_out);
}

// round 5
// speedup vs baseline: 1.7312x; 1.4554x over previous
#include <cuda_runtime.h>
#include <cuda_bf16.h>
#include <cstdint>

// ===================== problem constants =====================
#define N_ROWS 16384
#define DIMK   256
#define TILE   128
#define NBLK   (N_ROWS / TILE)   // 128 row-blocks
#define NCTA   128

// exp((s-1)/T) = 2^(s*C1 - C1),  C1 = log2(e)/T,  T = 0.07
#define C1F   20.60992915555662f
#define INV_T 14.285714285714286f

// ===================== device globals (no allocs allowed) =====================
__device__ uint4 g_emb4[N_ROWS * DIMK / 8];     // normalized bf16 rows
__device__ float g_acc[(size_t)NCTA * N_ROWS];  // per-CTA row-sum slabs (8 MB)
__device__ float g_diag[N_ROWS];
__device__ float g_partial[64];

// ===================== helpers =====================
__device__ __forceinline__ uint32_t smem_to_u32(const void* smem_ptr) {
    uint32_t addr;
    asm("{ .reg .u64 tmp; cvta.to.shared.u64 tmp, %1; cvt.u32.u64 %0, tmp; }"
        : "=r"(addr) : "l"(smem_ptr));
    return addr;
}

__device__ __forceinline__ void ldsm4(uint32_t* r, uint32_t addr) {
    asm volatile("ldmatrix.sync.aligned.m8n8.x4.shared.b16 {%0,%1,%2,%3}, [%4];"
        : "=r"(r[0]), "=r"(r[1]), "=r"(r[2]), "=r"(r[3]) : "r"(addr));
}

__device__ __forceinline__ void mma16816(float* c, const uint32_t* a, uint32_t b0, uint32_t b1) {
    asm volatile(
        "mma.sync.aligned.m16n8k16.row.col.f32.bf16.bf16.f32 "
        "{%0,%1,%2,%3}, {%4,%5,%6,%7}, {%8,%9}, {%0,%1,%2,%3};"
        : "+f"(c[0]), "+f"(c[1]), "+f"(c[2]), "+f"(c[3])
        : "r"(a[0]), "r"(a[1]), "r"(a[2]), "r"(a[3]), "r"(b0), "r"(b1));
}

__device__ __forceinline__ void mma16816_z(float* c, const uint32_t* a, uint32_t b0, uint32_t b1) {
    asm volatile(
        "mma.sync.aligned.m16n8k16.row.col.f32.bf16.bf16.f32 "
        "{%0,%1,%2,%3}, {%4,%5,%6,%7}, {%8,%9}, {%10,%10,%10,%10};"
        : "=f"(c[0]), "=f"(c[1]), "=f"(c[2]), "=f"(c[3])
        : "r"(a[0]), "r"(a[1]), "r"(a[2]), "r"(a[3]), "r"(b0), "r"(b1), "f"(0.0f));
}

__device__ __forceinline__ float ex2f(float x) {
    float r;
    asm("ex2.approx.f32 %0, %1;" : "=f"(r) : "f"(x));
    return r;
}

#define CP_ASYNC16(dst_u32, src_ptr) \
    asm volatile("cp.async.cg.shared.global [%0], [%1], 16;" \
        :: "r"(dst_u32), "l"(src_ptr) : "memory")
#define CP_COMMIT() asm volatile("cp.async.commit_group;" ::: "memory")
#define CP_WAIT0()  asm volatile("cp.async.wait_group 0;" ::: "memory")
#define CP_WAIT1()  asm volatile("cp.async.wait_group 1;" ::: "memory")

// ===================== kernel 1: L2-normalize rows + zero slabs =====================
__global__ __launch_bounds__(256) void norm_kernel(const float* __restrict__ in) {
    // zero g_acc: 2048 blocks * 256 thr = 524288 threads, 2M elems -> 4 each
    size_t zt = (size_t)blockIdx.x * 256 + threadIdx.x;
#pragma unroll
    for (int z = 0; z < 4; z++)
        g_acc[zt + (size_t)z * 524288] = 0.0f;

    int wid = threadIdx.x >> 5;
    int lane = threadIdx.x & 31;
    int row = blockIdx.x * 8 + wid;

    const float4* p = reinterpret_cast<const float4*>(in + (size_t)row * DIMK) + lane * 2;
    float4 a = p[0];
    float4 b = p[1];
    float ss = a.x * a.x + a.y * a.y + a.z * a.z + a.w * a.w
             + b.x * b.x + b.y * b.y + b.z * b.z + b.w * b.w;
#pragma unroll
    for (int o = 16; o > 0; o >>= 1) ss += __shfl_xor_sync(0xffffffffu, ss, o);

    float nrm = fmaxf(sqrtf(ss), 1e-12f);
    float sc = 1.0f / nrm;

    __nv_bfloat162 h0 = __floats2bfloat162_rn(a.x * sc, a.y * sc);
    __nv_bfloat162 h1 = __floats2bfloat162_rn(a.z * sc, a.w * sc);
    __nv_bfloat162 h2 = __floats2bfloat162_rn(b.x * sc, b.y * sc);
    __nv_bfloat162 h3 = __floats2bfloat162_rn(b.z * sc, b.w * sc);
    uint4 u;
    u.x = *reinterpret_cast<uint32_t*>(&h0);
    u.y = *reinterpret_cast<uint32_t*>(&h1);
    u.z = *reinterpret_cast<uint32_t*>(&h2);
    u.w = *reinterpret_cast<uint32_t*>(&h3);
    g_emb4[(size_t)row * 32 + lane] = u;
}

// ===================== kernel 2: upper-triangle GEMM + symmetric LSE accumulation =====================
// SMEM: A @0 (64KB), B buf0 @64K, B buf1 @128K, tail: s_colp[128], s_rowp[512]
#define SM_A     0
#define SM_B     65536
#define SM_TAIL  196608
#define OFF_COLP 0
#define OFF_ROWP 512
#define DYN_SMEM (196608 + 512 + 2048)

__device__ __forceinline__ void load_tile_async(uint32_t dst_u, int row0, int tid) {
#pragma unroll
    for (int it = 0; it < 16; ++it) {
        int c = tid + it * 256;
        int i = c >> 5;
        int j = c & 31;
        uint32_t off = ((uint32_t)i << 9) + ((uint32_t)(j ^ (i & 7)) << 4);
        CP_ASYNC16(dst_u + off, &g_emb4[(size_t)(row0 + i) * 32 + j]);
    }
}

__device__ __forceinline__ void epi_step(
    const float (&accP)[4][4][4], int v, float (&rowacc)[8], float (&colacc)[8],
    bool diag_tile, int Iglob, int warp_m, int warp_n, int g, int tg)
{
    int mf = v >> 4, nf = (v >> 2) & 3, e = v & 3;
    float s = accP[mf][nf][e];
    float ex = ex2f(fmaf(s, C1F, -C1F));     // exp((s-1)/T)
    rowacc[mf * 2 + (e >> 1)] += ex;
    colacc[nf * 2 + (e & 1)] += ex;
    if (diag_tile) {
        int r = warp_m * 64 + mf * 16 + g + ((e >> 1) << 3);
        int cc = warp_n * 32 + nf * 8 + (tg << 1) + (e & 1);
        if (r == cc) g_diag[Iglob * TILE + r] = s;
    }
}

__device__ __forceinline__ void drain_epi(
    const float (&accP)[4][4][4], float (&rowacc)[8], float (&colacc)[8],
    bool diag_tile, int Iglob, int warp_m, int warp_n, int g, int tg)
{
#pragma unroll
    for (int v = 0; v < 64; v++)
        epi_step(accP, v, rowacc, colacc, diag_tile, Iglob, warp_m, warp_n, g, tg);
}

// Reduce colacc across lanes, combine warp_m halves in smem, += into this CTA's slab.
// Contains one __syncthreads (S2).
__device__ __forceinline__ void col_flush(
    float (&colacc)[8], bool skip, int Jglob, int cta,
    float* s_colp, int warp_m, int warp_n, int lane)
{
    float red[8];
#pragma unroll
    for (int j = 0; j < 8; j++) {
        float v = colacc[j];
        v += __shfl_xor_sync(0xffffffffu, v, 4);
        v += __shfl_xor_sync(0xffffffffu, v, 8);
        v += __shfl_xor_sync(0xffffffffu, v, 16);
        red[j] = v;
        colacc[j] = 0.0f;
    }
    if (warp_m == 0 && lane < 4) {
#pragma unroll
        for (int j = 0; j < 8; j++)
            s_colp[warp_n * 32 + (j >> 1) * 8 + lane * 2 + (j & 1)] = red[j];
    }
    __syncthreads();   // S2
    if (warp_m == 1 && lane < 4 && !skip) {
        size_t base = (size_t)cta * N_ROWS + (size_t)Jglob * TILE;
        float gv[8];
#pragma unroll
        for (int j = 0; j < 8; j++) {
            int cc = warp_n * 32 + (j >> 1) * 8 + lane * 2 + (j & 1);
            gv[j] = g_acc[base + cc];
        }
#pragma unroll
        for (int j = 0; j < 8; j++) {
            int cc = warp_n * 32 + (j >> 1) * 8 + lane * 2 + (j & 1);
            g_acc[base + cc] = gv[j] + s_colp[cc] + red[j];
        }
    }
}

template <bool DO_EPI>
__device__ __forceinline__ void mma_tile(
    uint32_t b_u, float (&accC)[4][4][4], const float (&accP)[4][4][4],
    const uint32_t (&a_base)[4], const uint32_t (&a_rx)[4], uint32_t a_hi,
    const uint32_t (&b_roff)[2], uint32_t b_rx, uint32_t b_kb,
    float (&rowacc)[8], float (&colacc)[8],
    bool diag_prev, int Iglob, int warp_m, int warp_n, int g, int tg)
{
#pragma unroll
    for (int ks = 0; ks < 16; ks++) {
        uint32_t a[4][4];
#pragma unroll
        for (int mf = 0; mf < 4; mf++) {
            uint32_t ch = ((uint32_t)(ks * 2) + a_hi) ^ a_rx[mf];
            ldsm4(a[mf], a_base[mf] + (ch << 4));
        }
        uint32_t b[2][4];
#pragma unroll
        for (int np = 0; np < 2; np++) {
            uint32_t ch = ((uint32_t)(ks * 2) + b_kb) ^ b_rx;
            ldsm4(b[np], b_u + b_roff[np] + (ch << 4));
        }
#pragma unroll
        for (int mf = 0; mf < 4; mf++)
#pragma unroll
            for (int np = 0; np < 2; np++) {
                if (ks == 0) {
                    mma16816_z(accC[mf][np * 2 + 0], a[mf], b[np][0], b[np][1]);
                    mma16816_z(accC[mf][np * 2 + 1], a[mf], b[np][2], b[np][3]);
                } else {
                    mma16816(accC[mf][np * 2 + 0], a[mf], b[np][0], b[np][1]);
                    mma16816(accC[mf][np * 2 + 1], a[mf], b[np][2], b[np][3]);
                }
            }
        if (DO_EPI) {
#pragma unroll
            for (int u = 0; u < 4; u++)
                epi_step(accP, ks * 4 + u, rowacc, colacc, diag_prev,
                         Iglob, warp_m, warp_n, g, tg);
        }
    }
}

__global__ __launch_bounds__(256, 1) void gemm_lse_kernel() {
    extern __shared__ char smem[];
    uint32_t su = smem_to_u32(smem);

    int tid = threadIdx.x;
    int lane = tid & 31;
    int wid = tid >> 5;
    int warp_m = wid >> 2;
    int warp_n = wid & 3;
    const int g = lane >> 2;
    const int tg = lane & 3;
    const int cta = (int)blockIdx.x;

    float* s_colp = reinterpret_cast<float*>(smem + SM_TAIL + OFF_COLP);
    float* s_rowp = reinterpret_cast<float*>(smem + SM_TAIL + OFF_ROWP);

    // Work assignment: pair-group gg = cta>>1 covers row-blocks gg and 127-gg
    // (129 tiles total). Even CTA: (gg, J=gg..gg+64) [65 tiles].
    // Odd CTA: (gg, J=gg+65..127) [63-gg tiles] then (127-gg, J=127-gg..127) [gg+1].
    int gg = cta >> 1;
    int sI[2], sJ0[2], sCnt[2];
    int ns = 0;
    if ((cta & 1) == 0) {
        sI[0] = gg; sJ0[0] = gg; sCnt[0] = 65; ns = 1;
    } else {
        if (gg < 63) { sI[ns] = gg; sJ0[ns] = gg + 65; sCnt[ns] = 63 - gg; ns++; }
        sI[ns] = 127 - gg; sJ0[ns] = 127 - gg; sCnt[ns] = gg + 1; ns++;
    }

    // ldmatrix addressing (A buffer fixed at SM_A)
    uint32_t a_base[4];
    uint32_t a_rx[4];
#pragma unroll
    for (int mf = 0; mf < 4; mf++) {
        int r = warp_m * 64 + mf * 16 + (lane & 15);
        a_base[mf] = su + SM_A + ((uint32_t)r << 9);
        a_rx[mf] = (uint32_t)(r & 7);
    }
    uint32_t a_hi = (uint32_t)(lane >> 4);

    int nB = (lane & 7) + ((lane >> 4) << 3);
    uint32_t b_roff[2];
#pragma unroll
    for (int np = 0; np < 2; np++)
        b_roff[np] = (uint32_t)((warp_n * 32 + np * 16 + nB) << 9);
    uint32_t b_rx = (uint32_t)(lane & 7);
    uint32_t b_kb = (uint32_t)((lane >> 3) & 1);

    float colacc[8];
#pragma unroll
    for (int j = 0; j < 8; j++) colacc[j] = 0.0f;

    float accA[4][4][4], accB[4][4][4];

    for (int sw = 0; sw < ns; sw++) {
        int I = sI[sw], J0 = sJ0[sw], cnt = sCnt[sw];
        float rowacc[8];
#pragma unroll
        for (int j = 0; j < 8; j++) rowacc[j] = 0.0f;

        load_tile_async(su + SM_A, I * TILE, tid);
        load_tile_async(su + SM_B, J0 * TILE, tid);
        CP_COMMIT();
        CP_WAIT0();
        __syncthreads();

        for (int i = 0; i < cnt; i++) {
            if (i + 1 < cnt) {
                load_tile_async(su + SM_B + ((i + 1) & 1) * 65536, (J0 + i + 1) * TILE, tid);
                CP_COMMIT();
                CP_WAIT1();
            } else {
                CP_WAIT0();
            }
            __syncthreads();   // S1: B(i) ready

            uint32_t b_u = su + SM_B + (i & 1) * 65536;
            bool diag_prev = (i == 1) && (J0 == I);

            if ((i & 1) == 0) {
                if (i > 0)
                    mma_tile<true>(b_u, accA, accB, a_base, a_rx, a_hi, b_roff, b_rx, b_kb,
                                   rowacc, colacc, diag_prev, I, warp_m, warp_n, g, tg);
                else
                    mma_tile<false>(b_u, accA, accB, a_base, a_rx, a_hi, b_roff, b_rx, b_kb,
                                    rowacc, colacc, false, I, warp_m, warp_n, g, tg);
            } else {
                mma_tile<true>(b_u, accB, accA, a_base, a_rx, a_hi, b_roff, b_rx, b_kb,
                               rowacc, colacc, diag_prev, I, warp_m, warp_n, g, tg);
            }

            if (i > 0)
                col_flush(colacc, diag_prev, J0 + i - 1, cta, s_colp, warp_m, warp_n, lane);
            else
                __syncthreads();   // S2 placeholder (buffer protection)
        }

        // Drain the last tile's epilogue
        bool last_diag = (cnt == 1) && (J0 == I);
        if ((cnt - 1) & 1)
            drain_epi(accB, rowacc, colacc, last_diag, I, warp_m, warp_n, g, tg);
        else
            drain_epi(accA, rowacc, colacc, last_diag, I, warp_m, warp_n, g, tg);
        col_flush(colacc, last_diag, J0 + cnt - 1, cta, s_colp, warp_m, warp_n, lane);

        // Row flush: reduce over tg lanes + 4 warp_n partials, += into slab
#pragma unroll
        for (int j = 0; j < 8; j++) {
            float v = rowacc[j];
            v += __shfl_xor_sync(0xffffffffu, v, 1);
            v += __shfl_xor_sync(0xffffffffu, v, 2);
            if (tg == 0) {
                int r = warp_m * 64 + (j >> 1) * 16 + g + ((j & 1) << 3);
                s_rowp[r * 4 + warp_n] = v;
            }
        }
        __syncthreads();
        if (tid < 128) {
            float S = s_rowp[tid * 4 + 0] + s_rowp[tid * 4 + 1]
                    + s_rowp[tid * 4 + 2] + s_rowp[tid * 4 + 3];
            g_acc[(size_t)cta * N_ROWS + (size_t)I * TILE + tid] += S;
        }
        __syncthreads();   // protect A/B buffers before next sweep's loads
    }
}

// ===================== kernel 3: per-row loss + block partial =====================
__global__ __launch_bounds__(256) void reduce_rows_kernel() {
    __shared__ float s_red[8];
    int r = blockIdx.x * 256 + threadIdx.x;
    float S = 0.0f;
#pragma unroll 4
    for (int c = 0; c < NCTA; c++)
        S += g_acc[(size_t)c * N_ROWS + r];
    float li = (1.0f - g_diag[r]) * INV_T + logf(S);
#pragma unroll
    for (int o = 16; o > 0; o >>= 1) li += __shfl_xor_sync(0xffffffffu, li, o);
    int lane = threadIdx.x & 31;
    int wid = threadIdx.x >> 5;
    if (lane == 0) s_red[wid] = li;
    __syncthreads();
    if (threadIdx.x == 0) {
        float v = 0.0f;
#pragma unroll
        for (int w = 0; w < 8; w++) v += s_red[w];
        g_partial[blockIdx.x] = v;
    }
}

// ===================== kernel 4: final scalar =====================
__global__ __launch_bounds__(64) void reduce_final_kernel(float* __restrict__ out) {
    __shared__ float s2[2];
    int tid = threadIdx.x;
    float v = g_partial[tid];
#pragma unroll
    for (int o = 16; o > 0; o >>= 1) v += __shfl_xor_sync(0xffffffffu, v, o);
    if ((tid & 31) == 0) s2[tid >> 5] = v;
    __syncthreads();
    if (tid == 0)
        out[0] = (s2[0] + s2[1]) * (1.0f / (float)N_ROWS);
}

// ===================== launch =====================
extern "C" void kernel_launch(void* const* d_in, const int* in_sizes, int n_in,
                              void* d_out, int out_size) {
    (void)in_sizes; (void)n_in; (void)out_size;
    const float* emb = (const float*)d_in[0];

    cudaFuncSetAttribute(gemm_lse_kernel,
                         cudaFuncAttributeMaxDynamicSharedMemorySize, DYN_SMEM);

    norm_kernel<<<N_ROWS / 8, 256>>>(emb);
    gemm_lse_kernel<<<NCTA, 256, DYN_SMEM>>>();
    reduce_rows_kernel<<<64, 256>>>();
    reduce_final_kernel<<<1, 64>>>((float*)d_out);
}

// round 6
// speedup vs baseline: 1.7341x; 1.0017x over previous
#include <cuda_runtime.h>
#include <cuda_bf16.h>
#include <cstdint>

// ===================== problem constants =====================
#define N_ROWS 16384
#define DIMK   256
#define TILE   128
#define NCTA   148
#define NTILES_TRI 8256          // 128*129/2

// exp((s-1)/T) = 2^(s*C1 - C1),  C1 = log2(e)/T,  T = 0.07
#define C1F   20.60992915555662f
#define INV_T 14.285714285714286f

// ===================== device globals (no allocs allowed) =====================
__device__ uint4 g_emb4[N_ROWS * DIMK / 8];   // normalized bf16 rows
__device__ float g_sum[N_ROWS];               // Σ_j exp((s_rj-1)/T) per row (atomic)
__device__ float g_diag[N_ROWS];
__device__ unsigned int g_done = 0;

// ===================== helpers =====================
__device__ __forceinline__ uint32_t smem_to_u32(const void* smem_ptr) {
    uint32_t addr;
    asm("{ .reg .u64 tmp; cvta.to.shared.u64 tmp, %1; cvt.u32.u64 %0, tmp; }"
        : "=r"(addr) : "l"(smem_ptr));
    return addr;
}

__device__ __forceinline__ void ldsm4(uint32_t* r, uint32_t addr) {
    asm volatile("ldmatrix.sync.aligned.m8n8.x4.shared.b16 {%0,%1,%2,%3}, [%4];"
        : "=r"(r[0]), "=r"(r[1]), "=r"(r[2]), "=r"(r[3]) : "r"(addr));
}

__device__ __forceinline__ void mma16816(float* c, const uint32_t* a, uint32_t b0, uint32_t b1) {
    asm volatile(
        "mma.sync.aligned.m16n8k16.row.col.f32.bf16.bf16.f32 "
        "{%0,%1,%2,%3}, {%4,%5,%6,%7}, {%8,%9}, {%0,%1,%2,%3};"
        : "+f"(c[0]), "+f"(c[1]), "+f"(c[2]), "+f"(c[3])
        : "r"(a[0]), "r"(a[1]), "r"(a[2]), "r"(a[3]), "r"(b0), "r"(b1));
}

__device__ __forceinline__ void mma16816_z(float* c, const uint32_t* a, uint32_t b0, uint32_t b1) {
    asm volatile(
        "mma.sync.aligned.m16n8k16.row.col.f32.bf16.bf16.f32 "
        "{%0,%1,%2,%3}, {%4,%5,%6,%7}, {%8,%9}, {%10,%10,%10,%10};"
        : "=f"(c[0]), "=f"(c[1]), "=f"(c[2]), "=f"(c[3])
        : "r"(a[0]), "r"(a[1]), "r"(a[2]), "r"(a[3]), "r"(b0), "r"(b1), "f"(0.0f));
}

__device__ __forceinline__ float ex2f(float x) {
    float r;
    asm("ex2.approx.f32 %0, %1;" : "=f"(r) : "f"(x));
    return r;
}

__device__ __forceinline__ void red_add(float* p, float v) {
    asm volatile("red.global.add.f32 [%0], %1;" :: "l"(p), "f"(v) : "memory");
}

#define CP_ASYNC16(dst_u32, src_ptr) \
    asm volatile("cp.async.cg.shared.global [%0], [%1], 16;" \
        :: "r"(dst_u32), "l"(src_ptr) : "memory")
#define CP_COMMIT() asm volatile("cp.async.commit_group;" ::: "memory")
#define CP_WAIT0()  asm volatile("cp.async.wait_group 0;" ::: "memory")
#define CP_WAIT1()  asm volatile("cp.async.wait_group 1;" ::: "memory")

// ===================== kernel 1: L2-normalize rows + zero accumulators =====================
__global__ __launch_bounds__(256) void norm_kernel(const float* __restrict__ in) {
    size_t gid = (size_t)blockIdx.x * 256 + threadIdx.x;
    if (gid < N_ROWS) g_sum[gid] = 0.0f;
    if (gid == 0) g_done = 0;

    int wid = threadIdx.x >> 5;
    int lane = threadIdx.x & 31;
    int row = blockIdx.x * 8 + wid;

    const float4* p = reinterpret_cast<const float4*>(in + (size_t)row * DIMK) + lane * 2;
    float4 a = p[0];
    float4 b = p[1];
    float ss = a.x * a.x + a.y * a.y + a.z * a.z + a.w * a.w
             + b.x * b.x + b.y * b.y + b.z * b.z + b.w * b.w;
#pragma unroll
    for (int o = 16; o > 0; o >>= 1) ss += __shfl_xor_sync(0xffffffffu, ss, o);

    float nrm = fmaxf(sqrtf(ss), 1e-12f);
    float sc = 1.0f / nrm;

    __nv_bfloat162 h0 = __floats2bfloat162_rn(a.x * sc, a.y * sc);
    __nv_bfloat162 h1 = __floats2bfloat162_rn(a.z * sc, a.w * sc);
    __nv_bfloat162 h2 = __floats2bfloat162_rn(b.x * sc, b.y * sc);
    __nv_bfloat162 h3 = __floats2bfloat162_rn(b.z * sc, b.w * sc);
    uint4 u;
    u.x = *reinterpret_cast<uint32_t*>(&h0);
    u.y = *reinterpret_cast<uint32_t*>(&h1);
    u.z = *reinterpret_cast<uint32_t*>(&h2);
    u.w = *reinterpret_cast<uint32_t*>(&h3);
    g_emb4[(size_t)row * 32 + lane] = u;
}

// ===================== kernel 2: triangular GEMM + symmetric LSE + final reduce =====================
// SMEM: A @0 (64KB), B buf0 @64K, B buf1 @128K, s_red[8] tail
#define SM_A     0
#define SM_B     65536
#define SM_TAIL  196608
#define DYN_SMEM (196608 + 64)

__device__ __forceinline__ void load_tile_async(uint32_t dst_u, int row0, int tid) {
#pragma unroll
    for (int it = 0; it < 16; ++it) {
        int c = tid + it * 256;
        int i = c >> 5;
        int j = c & 31;
        uint32_t off = ((uint32_t)i << 9) + ((uint32_t)(j ^ (i & 7)) << 4);
        CP_ASYNC16(dst_u + off, &g_emb4[(size_t)(row0 + i) * 32 + j]);
    }
}

__device__ __forceinline__ void epi_step(
    const float (&accP)[4][4][4], int v, float (&rowacc)[8], float (&colacc)[8],
    bool diag_tile, int Iglob, int warp_m, int warp_n, int g, int tg)
{
    int mf = v >> 4, nf = (v >> 2) & 3, e = v & 3;
    float s = accP[mf][nf][e];
    float ex = ex2f(fmaf(s, C1F, -C1F));     // exp((s-1)/T)
    rowacc[mf * 2 + (e >> 1)] += ex;
    colacc[nf * 2 + (e & 1)] += ex;
    if (diag_tile) {
        int r = warp_m * 64 + mf * 16 + g + ((e >> 1) << 3);
        int cc = warp_n * 32 + nf * 8 + (tg << 1) + (e & 1);
        if (r == cc) g_diag[Iglob * TILE + r] = s;
    }
}

__device__ __forceinline__ void drain_epi(
    const float (&accP)[4][4][4], float (&rowacc)[8], float (&colacc)[8],
    bool diag_tile, int Iglob, int warp_m, int warp_n, int g, int tg)
{
#pragma unroll
    for (int v = 0; v < 64; v++)
        epi_step(accP, v, rowacc, colacc, diag_tile, Iglob, warp_m, warp_n, g, tg);
}

// Column flush: shfl-reduce over the 8 g-lanes, then lanes 0-3 RED their 8 cols.
// Both warp_m halves RED independently (atomics merge). No barrier, no smem.
__device__ __forceinline__ void col_flush(
    float (&colacc)[8], bool skip, int Jglob, int warp_n, int lane)
{
#pragma unroll
    for (int j = 0; j < 8; j++) {
        float v = colacc[j];
        v += __shfl_xor_sync(0xffffffffu, v, 4);
        v += __shfl_xor_sync(0xffffffffu, v, 8);
        v += __shfl_xor_sync(0xffffffffu, v, 16);
        if (lane < 4 && !skip) {
            int cc = warp_n * 32 + (j >> 1) * 8 + lane * 2 + (j & 1);
            red_add(&g_sum[Jglob * TILE + cc], v);
        }
        colacc[j] = 0.0f;
    }
}

template <bool DO_EPI>
__device__ __forceinline__ void mma_tile(
    uint32_t b_u, float (&accC)[4][4][4], const float (&accP)[4][4][4],
    const uint32_t (&a_base)[4], const uint32_t (&a_rx)[4], uint32_t a_hi,
    const uint32_t (&b_roff)[2], uint32_t b_rx, uint32_t b_kb,
    float (&rowacc)[8], float (&colacc)[8],
    bool diag_prev, int Iglob, int warp_m, int warp_n, int g, int tg)
{
#pragma unroll
    for (int ks = 0; ks < 16; ks++) {
        uint32_t a[4][4];
#pragma unroll
        for (int mf = 0; mf < 4; mf++) {
            uint32_t ch = ((uint32_t)(ks * 2) + a_hi) ^ a_rx[mf];
            ldsm4(a[mf], a_base[mf] + (ch << 4));
        }
        uint32_t b[2][4];
#pragma unroll
        for (int np = 0; np < 2; np++) {
            uint32_t ch = ((uint32_t)(ks * 2) + b_kb) ^ b_rx;
            ldsm4(b[np], b_u + b_roff[np] + (ch << 4));
        }
#pragma unroll
        for (int mf = 0; mf < 4; mf++)
#pragma unroll
            for (int np = 0; np < 2; np++) {
                if (ks == 0) {
                    mma16816_z(accC[mf][np * 2 + 0], a[mf], b[np][0], b[np][1]);
                    mma16816_z(accC[mf][np * 2 + 1], a[mf], b[np][2], b[np][3]);
                } else {
                    mma16816(accC[mf][np * 2 + 0], a[mf], b[np][0], b[np][1]);
                    mma16816(accC[mf][np * 2 + 1], a[mf], b[np][2], b[np][3]);
                }
            }
        if (DO_EPI) {
#pragma unroll
            for (int u = 0; u < 4; u++)
                epi_step(accP, ks * 4 + u, rowacc, colacc, diag_prev,
                         Iglob, warp_m, warp_n, g, tg);
        }
    }
}

__global__ __launch_bounds__(256, 1) void gemm_lse_kernel(float* __restrict__ out) {
    extern __shared__ char smem[];
    uint32_t su = smem_to_u32(smem);
    float* s_red = reinterpret_cast<float*>(smem + SM_TAIL);
    __shared__ unsigned int s_ticket;

    int tid = threadIdx.x;
    int lane = tid & 31;
    int wid = tid >> 5;
    int warp_m = wid >> 2;
    int warp_n = wid & 3;
    const int g = lane >> 2;
    const int tg = lane & 3;
    const int cta = (int)blockIdx.x;

    // ldmatrix addressing (A buffer fixed at SM_A)
    uint32_t a_base[4];
    uint32_t a_rx[4];
#pragma unroll
    for (int mf = 0; mf < 4; mf++) {
        int r = warp_m * 64 + mf * 16 + (lane & 15);
        a_base[mf] = su + SM_A + ((uint32_t)r << 9);
        a_rx[mf] = (uint32_t)(r & 7);
    }
    uint32_t a_hi = (uint32_t)(lane >> 4);

    int nB = (lane & 7) + ((lane >> 4) << 3);
    uint32_t b_roff[2];
#pragma unroll
    for (int np = 0; np < 2; np++)
        b_roff[np] = (uint32_t)((warp_n * 32 + np * 16 + nB) << 9);
    uint32_t b_rx = (uint32_t)(lane & 7);
    uint32_t b_kb = (uint32_t)((lane >> 3) & 1);

    float colacc[8];
#pragma unroll
    for (int j = 0; j < 8; j++) colacc[j] = 0.0f;

    float accA[4][4][4], accB[4][4][4];

    // Balanced triangular chunking: tiles linearized as pair q = (row q: J=q..127,
    // then row 127-q: J=127-q..127), 129 tiles per pair, 64 pairs = 8256 tiles.
    // CTA c gets a contiguous range of 55/56 tiles (first 116 CTAs get 56).
    int t_beg = cta * 55 + (cta < 116 ? cta : 116);
    int t_end = t_beg + 55 + (cta < 116 ? 1 : 0);

    int t = t_beg;
    while (t < t_end) {
        int q = t / 129;
        int r = t - q * 129;
        int I, J0, rowrem;
        if (r < 128 - q) { I = q; J0 = q + r; rowrem = 128 - q - r; }
        else { int r2 = r - (128 - q); I = 127 - q; J0 = 127 - q + r2; rowrem = q + 1 - r2; }
        int cnt = min(t_end - t, rowrem);

        // ---------------- sweep: A = block I, B = blocks J0..J0+cnt-1 ----------------
        float rowacc[8];
#pragma unroll
        for (int j = 0; j < 8; j++) rowacc[j] = 0.0f;

        load_tile_async(su + SM_A, I * TILE, tid);
        load_tile_async(su + SM_B, J0 * TILE, tid);
        CP_COMMIT();
        CP_WAIT0();
        __syncthreads();

        for (int i = 0; i < cnt; i++) {
            if (i + 1 < cnt) {
                load_tile_async(su + SM_B + ((i + 1) & 1) * 65536, (J0 + i + 1) * TILE, tid);
                CP_COMMIT();
                CP_WAIT1();
            } else {
                CP_WAIT0();
            }
            __syncthreads();   // S1: B(i) visible to all warps

            uint32_t b_u = su + SM_B + (i & 1) * 65536;
            bool diag_prev = (i == 1) && (J0 == I);

            if ((i & 1) == 0) {
                if (i > 0)
                    mma_tile<true>(b_u, accA, accB, a_base, a_rx, a_hi, b_roff, b_rx, b_kb,
                                   rowacc, colacc, diag_prev, I, warp_m, warp_n, g, tg);
                else
                    mma_tile<false>(b_u, accA, accB, a_base, a_rx, a_hi, b_roff, b_rx, b_kb,
                                    rowacc, colacc, false, I, warp_m, warp_n, g, tg);
            } else {
                mma_tile<true>(b_u, accB, accA, a_base, a_rx, a_hi, b_roff, b_rx, b_kb,
                               rowacc, colacc, diag_prev, I, warp_m, warp_n, g, tg);
            }

            if (i > 0)
                col_flush(colacc, diag_prev, J0 + i - 1, warp_n, lane);
            __syncthreads();   // S2: all warps done reading buf[i&1] before refill
        }

        // Drain the last tile's epilogue
        bool last_diag = (cnt == 1) && (J0 == I);
        if ((cnt - 1) & 1)
            drain_epi(accB, rowacc, colacc, last_diag, I, warp_m, warp_n, g, tg);
        else
            drain_epi(accA, rowacc, colacc, last_diag, I, warp_m, warp_n, g, tg);
        col_flush(colacc, last_diag, J0 + cnt - 1, warp_n, lane);

        // Row flush: reduce over tg lanes, RED per warp (4 warp_n merge via atomics)
#pragma unroll
        for (int j = 0; j < 8; j++) {
            float v = rowacc[j];
            v += __shfl_xor_sync(0xffffffffu, v, 1);
            v += __shfl_xor_sync(0xffffffffu, v, 2);
            if (tg == 0) {
                int rr = warp_m * 64 + (j >> 1) * 16 + g + ((j & 1) << 3);
                red_add(&g_sum[I * TILE + rr], v);
            }
        }
        __syncthreads();   // protect A/B buffers before next sweep's loads

        t += cnt;
    }

    // ---------------- last-CTA final reduction ----------------
    __threadfence();
    __syncthreads();
    if (tid == 0) s_ticket = atomicAdd(&g_done, 1u);
    __syncthreads();
    if (s_ticket == (unsigned)(gridDim.x - 1)) {
        __threadfence();
        float part = 0.0f;
#pragma unroll 4
        for (int rr = tid; rr < N_ROWS; rr += 256) {
            float S = g_sum[rr];
            part += (1.0f - g_diag[rr]) * INV_T + __logf(S);
        }
#pragma unroll
        for (int o = 16; o > 0; o >>= 1) part += __shfl_xor_sync(0xffffffffu, part, o);
        if (lane == 0) s_red[wid] = part;
        __syncthreads();
        if (tid == 0) {
            float v = 0.0f;
#pragma unroll
            for (int w = 0; w < 8; w++) v += s_red[w];
            out[0] = v * (1.0f / (float)N_ROWS);
            g_done = 0;   // reset for next graph replay
        }
    }
}

// ===================== launch =====================
extern "C" void kernel_launch(void* const* d_in, const int* in_sizes, int n_in,
                              void* d_out, int out_size) {
    (void)in_sizes; (void)n_in; (void)out_size;
    const float* emb = (const float*)d_in[0];

    cudaFuncSetAttribute(gemm_lse_kernel,
                         cudaFuncAttributeMaxDynamicSharedMemorySize, DYN_SMEM);

    norm_kernel<<<N_ROWS / 8, 256>>>(emb);
    gemm_lse_kernel<<<NCTA, 256, DYN_SMEM>>>((float*)d_out);
}